// round 9
// baseline (speedup 1.0000x reference)
#include <cuda_runtime.h>

#define BATCH 256
#define SEQ   2048
#define EMBD  16
#define HIDD  32
#define GATE  128

typedef unsigned long long u64;
typedef unsigned int       u32;

// 256 MB scratch: gate-packed input projection, float4(i,f,g,o) per (token, hid)
__device__ float4 g_zx[(size_t)BATCH * SEQ * HIDD];

__device__ __forceinline__ u64 pack2(float lo, float hi){
    u64 r; asm("mov.b64 %0, {%1,%2};" : "=l"(r) : "f"(lo), "f"(hi)); return r;
}
__device__ __forceinline__ void unpack2(u64 v, float& lo, float& hi){
    asm("mov.b64 {%0,%1}, %2;" : "=f"(lo), "=f"(hi) : "l"(v));
}
__device__ __forceinline__ u64 ffma2(u64 a, u64 b, u64 c){
    u64 d; asm("fma.rn.f32x2 %0, %1, %2, %3;" : "=l"(d) : "l"(a), "l"(b), "l"(c)); return d;
}
__device__ __forceinline__ float tanha(float x){
    float y; asm("tanh.approx.f32 %0, %1;" : "=f"(y) : "f"(x)); return y;
}
// sigmoid(z) = 0.5 + 0.5*tanh(z/2)
__device__ __forceinline__ float sigt(float z){
    return fmaf(0.5f, tanha(0.5f * z), 0.5f);
}
__device__ __forceinline__ u32 smem_u32(const void* p){
    u32 a;
    asm("{ .reg .u64 t; cvta.to.shared.u64 t, %1; cvt.u32.u64 %0, t; }"
        : "=r"(a) : "l"(p));
    return a;
}
// Ordered shared ops (asm volatile keeps program order; MIO executes same-warp
// shared accesses in order -> STS(h) visible to the next iteration's LDS
// without a WARPSYNC, since the branch-free warp never diverges).
__device__ __forceinline__ void sts32(u32 addr, float v){
    asm volatile("st.shared.f32 [%0], %1;" :: "r"(addr), "f"(v) : "memory");
}
__device__ __forceinline__ float4 lds128(u32 addr){
    float4 v;
    asm volatile("ld.shared.v4.f32 {%0,%1,%2,%3}, [%4];"
        : "=f"(v.x), "=f"(v.y), "=f"(v.z), "=f"(v.w) : "r"(addr));
    return v;
}

// ─────────────── Phase 1: zx = emb[tok]@Wk + b  (proven, ~85us) ─────────────
__global__ __launch_bounds__(256) void proj_kernel(
    const int*   __restrict__ tokens,
    const float* __restrict__ emb,
    const float* __restrict__ Wk,
    const float* __restrict__ bias)
{
    const int j    = threadIdx.x & 31;
    const int warp = (blockIdx.x << 3) + (threadIdx.x >> 5);
    const int base = warp << 8;

    u64 wk_if[EMBD], wk_go[EMBD];
    #pragma unroll
    for (int e = 0; e < EMBD; e++){
        wk_if[e] = pack2(Wk[e*GATE + j],      Wk[e*GATE + j + 32]);
        wk_go[e] = pack2(Wk[e*GATE + j + 64], Wk[e*GATE + j + 96]);
    }
    const u64 b_if = pack2(bias[j],      bias[j + 32]);
    const u64 b_go = pack2(bias[j + 64], bias[j + 96]);

    for (int s = 0; s < 256; s += 2){
        const int tflat = base + s + (j >> 4);
        const int tok   = tokens[tflat];
        const float xv  = emb[tok * EMBD + (j & 15)];

        u64 aI = b_if, aG = b_go;
        u64 cI = b_if, cG = b_go;
        #pragma unroll
        for (int e = 0; e < EMBD; e++){
            float xa = __shfl_sync(0xffffffffu, xv, e);
            float xb = __shfl_sync(0xffffffffu, xv, 16 + e);
            u64 xa2 = pack2(xa, xa);
            u64 xb2 = pack2(xb, xb);
            aI = ffma2(xa2, wk_if[e], aI);
            aG = ffma2(xa2, wk_go[e], aG);
            cI = ffma2(xb2, wk_if[e], cI);
            cG = ffma2(xb2, wk_go[e], cG);
        }
        float4 zA, zB;
        unpack2(aI, zA.x, zA.y); unpack2(aG, zA.z, zA.w);
        unpack2(cI, zB.x, zB.y); unpack2(cG, zB.z, zB.w);
        g_zx[(size_t)(base + s)     * HIDD + j] = zA;
        g_zx[(size_t)(base + s + 1) * HIDD + j] = zB;
    }
}

// ─────────────── Phase 2: single-warp recurrence, stall-squeezed ────────────
// One warp/sequence; lane j owns hid j + gate cols (j,j+32,j+64,j+96).
// No barriers at all: smem h handoff ordered by per-warp in-order MIO.
// i,f,g chains issue first; their MUFU/c-chain latency hides under the o-gate
// FFMA block and the prefetch LDGs. 128 scalar FFMA/step = 256-slot floor.
__global__ __launch_bounds__(32) void rec_kernel(
    const int*   __restrict__ tokens,
    const float* __restrict__ Wr,
    float*       __restrict__ out)
{
    __shared__ float hs[HIDD];

    const int b = blockIdx.x;
    const int j = threadIdx.x;

    float wi[HIDD], wf[HIDD], wg[HIDD], wo[HIDD];
    #pragma unroll
    for (int k = 0; k < HIDD; k++){
        wi[k] = Wr[k*GATE + j];
        wf[k] = Wr[k*GATE + j + 32];
        wg[k] = Wr[k*GATE + j + 64];
        wo[k] = Wr[k*GATE + j + 96];
    }

    const u32 hbase = smem_u32(hs);
    const u32 haddr = hbase + (u32)j * 4u;

    const float4* __restrict__ zp   = g_zx + (size_t)b * SEQ * HIDD + j;
    const int*    __restrict__ tptr = tokens + b * SEQ;
    float* optr = out + (size_t)b * SEQ * HIDD + j;

    float4 rz[4]; int rtok[4];
    #pragma unroll
    for (int p = 0; p < 3; p++){
        rz[p]   = zp[(size_t)p * HIDD];
        rtok[p] = tptr[p];
    }

    sts32(haddr, 0.0f);
    float h = 0.0f, c = 0.0f;

    #pragma unroll 4
    for (int t = 0; t < SEQ; t++){
        // h(t-1) broadcast: 8x LDS.128 (in-order after last iteration's STS)
        float hv[HIDD];
        #pragma unroll
        for (int qq = 0; qq < 8; qq++){
            float4 v = lds128(hbase + (u32)qq * 16u);
            hv[qq*4+0] = v.x; hv[qq*4+1] = v.y; hv[qq*4+2] = v.z; hv[qq*4+3] = v.w;
        }

        const float4 z4  = rz[t & 3];
        const int    tok = rtok[t & 3];

        // i, f, g chains first (their downstream latency hides under o + LDG)
        float i0 = z4.x, f0 = z4.y, g0 = z4.z;
        float i1 = 0.f,  f1 = 0.f,  g1 = 0.f;
        #pragma unroll
        for (int k = 0; k < 16; k++){
            i0 = fmaf(hv[k], wi[k], i0);
            f0 = fmaf(hv[k], wf[k], f0);
            g0 = fmaf(hv[k], wg[k], g0);
        }
        #pragma unroll
        for (int k = 16; k < 32; k++){
            i1 = fmaf(hv[k], wi[k], i1);
            f1 = fmaf(hv[k], wf[k], f1);
            g1 = fmaf(hv[k], wg[k], g1);
        }
        const float gi = sigt(i0 + i1);
        const float gf = sigt(f0 + f1);
        const float gg = tanha(g0 + g1);
        const float cn = fmaf(gf, c, gi * gg);
        const float tc = tanha(cn);

        // prefetch t+3 in the MUFU shadow (ring indices compile-time)
        const int pidx = min(t + 3, SEQ - 1);
        rz[(t + 3) & 3]   = zp[(size_t)pidx * HIDD];
        rtok[(t + 3) & 3] = tptr[pidx];

        // o chains last
        float o0 = z4.w, o1 = 0.f;
        #pragma unroll
        for (int k = 0; k < 16; k++)
            o0 = fmaf(hv[k], wo[k], o0);
        #pragma unroll
        for (int k = 16; k < 32; k++)
            o1 = fmaf(hv[k], wo[k], o1);
        const float go = sigt(o0 + o1);
        const float hn = go * tc;

        const bool m = (tok != 0);
        c = m ? cn : c;
        h = m ? hn : h;

        sts32(haddr, h);                     // next iteration's LDS sees this
        optr[(size_t)t * HIDD] = h;          // coalesced 128B per warp
    }
}

extern "C" void kernel_launch(void* const* d_in, const int* in_sizes, int n_in,
                              void* d_out, int out_size)
{
    (void)in_sizes; (void)n_in; (void)out_size;
    const int*   tokens = (const int*)  d_in[0];
    const float* emb    = (const float*)d_in[1];
    const float* Wk     = (const float*)d_in[2];
    const float* Wr     = (const float*)d_in[3];
    const float* bias   = (const float*)d_in[4];
    float* out = (float*)d_out;

    proj_kernel<<<BATCH, 256>>>(tokens, emb, Wk, bias);
    rec_kernel<<<BATCH, 32>>>(tokens, Wr, out);
}

// round 10
// speedup vs baseline: 1.0120x; 1.0120x over previous
#include <cuda_runtime.h>

#define BATCH 256
#define SEQ   2048
#define EMBD  16
#define HIDD  32
#define GATE  128
#define SEQ_PER_BLK 4

typedef unsigned long long u64;
typedef unsigned int       u32;

// 256 MB scratch: gate-packed input projection, float4(i,f,g,o) per (token, hid)
__device__ float4 g_zx[(size_t)BATCH * SEQ * HIDD];

__device__ __forceinline__ u64 pack2(float lo, float hi){
    u64 r; asm("mov.b64 %0, {%1,%2};" : "=l"(r) : "f"(lo), "f"(hi)); return r;
}
__device__ __forceinline__ void unpack2(u64 v, float& lo, float& hi){
    asm("mov.b64 {%0,%1}, %2;" : "=f"(lo), "=f"(hi) : "l"(v));
}
__device__ __forceinline__ u64 ffma2(u64 a, u64 b, u64 c){
    u64 d; asm("fma.rn.f32x2 %0, %1, %2, %3;" : "=l"(d) : "l"(a), "l"(b), "l"(c)); return d;
}
__device__ __forceinline__ float tanha(float x){
    float y; asm("tanh.approx.f32 %0, %1;" : "=f"(y) : "f"(x)); return y;
}
// sigmoid(z) = 0.5 + 0.5*tanh(z/2)
__device__ __forceinline__ float sigt(float z){
    return fmaf(0.5f, tanha(0.5f * z), 0.5f);
}
__device__ __forceinline__ u32 smem_u32(const void* p){
    u32 a;
    asm("{ .reg .u64 t; cvta.to.shared.u64 t, %1; cvt.u32.u64 %0, t; }"
        : "=r"(a) : "l"(p));
    return a;
}
// Ordered shared ops: asm volatile keeps program order; per-warp MIO executes
// shared accesses in order -> STS(h) visible to the next iteration's LDS
// without any barrier (warps never diverge and never share h segments).
__device__ __forceinline__ void sts32(u32 addr, float v){
    asm volatile("st.shared.f32 [%0], %1;" :: "r"(addr), "f"(v) : "memory");
}
__device__ __forceinline__ float4 lds128(u32 addr){
    float4 v;
    asm volatile("ld.shared.v4.f32 {%0,%1,%2,%3}, [%4];"
        : "=f"(v.x), "=f"(v.y), "=f"(v.z), "=f"(v.w) : "r"(addr));
    return v;
}

// ─────────────── Phase 1: zx = emb[tok]@Wk + b  (proven, ~85us) ─────────────
__global__ __launch_bounds__(256) void proj_kernel(
    const int*   __restrict__ tokens,
    const float* __restrict__ emb,
    const float* __restrict__ Wk,
    const float* __restrict__ bias)
{
    const int j    = threadIdx.x & 31;
    const int warp = (blockIdx.x << 3) + (threadIdx.x >> 5);
    const int base = warp << 8;

    u64 wk_if[EMBD], wk_go[EMBD];
    #pragma unroll
    for (int e = 0; e < EMBD; e++){
        wk_if[e] = pack2(Wk[e*GATE + j],      Wk[e*GATE + j + 32]);
        wk_go[e] = pack2(Wk[e*GATE + j + 64], Wk[e*GATE + j + 96]);
    }
    const u64 b_if = pack2(bias[j],      bias[j + 32]);
    const u64 b_go = pack2(bias[j + 64], bias[j + 96]);

    for (int s = 0; s < 256; s += 2){
        const int tflat = base + s + (j >> 4);
        const int tok   = tokens[tflat];
        const float xv  = emb[tok * EMBD + (j & 15)];

        u64 aI = b_if, aG = b_go;
        u64 cI = b_if, cG = b_go;
        #pragma unroll
        for (int e = 0; e < EMBD; e++){
            float xa = __shfl_sync(0xffffffffu, xv, e);
            float xb = __shfl_sync(0xffffffffu, xv, 16 + e);
            u64 xa2 = pack2(xa, xa);
            u64 xb2 = pack2(xb, xb);
            aI = ffma2(xa2, wk_if[e], aI);
            aG = ffma2(xa2, wk_go[e], aG);
            cI = ffma2(xb2, wk_if[e], cI);
            cG = ffma2(xb2, wk_go[e], cG);
        }
        float4 zA, zB;
        unpack2(aI, zA.x, zA.y); unpack2(aG, zA.z, zA.w);
        unpack2(cI, zB.x, zB.y); unpack2(cG, zB.z, zB.w);
        g_zx[(size_t)(base + s)     * HIDD + j] = zA;
        g_zx[(size_t)(base + s + 1) * HIDD + j] = zB;
    }
}

// ─────────────── Phase 2: 4 independent warps/block, one seq per warp ──────
// KEY FIX vs R9: 1-warp blocks all land on SMSP 0 (wid%4==0), so co-resident
// blocks serialized on one scheduler while 3 SMSPs idled. 4 warps/block puts
// each sequence on its own SMSP. Warps are fully independent: own smem h
// segment, barrier-free in-order STS->LDS handoff, branch-free body.
__global__ __launch_bounds__(128) void rec_kernel(
    const int*   __restrict__ tokens,
    const float* __restrict__ Wr,
    float*       __restrict__ out)
{
    __shared__ float hs[SEQ_PER_BLK][HIDD];

    const int w = threadIdx.x >> 5;              // warp -> SMSP w
    const int j = threadIdx.x & 31;
    const int b = blockIdx.x * SEQ_PER_BLK + w;  // sequence index

    float wi[HIDD], wf[HIDD], wg[HIDD], wo[HIDD];
    #pragma unroll
    for (int k = 0; k < HIDD; k++){
        wi[k] = Wr[k*GATE + j];
        wf[k] = Wr[k*GATE + j + 32];
        wg[k] = Wr[k*GATE + j + 64];
        wo[k] = Wr[k*GATE + j + 96];
    }

    const u32 hbase = smem_u32(hs[w]);
    const u32 haddr = hbase + (u32)j * 4u;

    const float4* __restrict__ zp   = g_zx + (size_t)b * SEQ * HIDD + j;
    const int*    __restrict__ tptr = tokens + b * SEQ;
    float* optr = out + (size_t)b * SEQ * HIDD + j;

    float4 rz[4]; int rtok[4];
    #pragma unroll
    for (int p = 0; p < 3; p++){
        rz[p]   = zp[(size_t)p * HIDD];
        rtok[p] = tptr[p];
    }

    sts32(haddr, 0.0f);
    float h = 0.0f, c = 0.0f;

    #pragma unroll 4
    for (int t = 0; t < SEQ; t++){
        // h(t-1) broadcast: 8x LDS.128 (in-order after last iteration's STS)
        float hv[HIDD];
        #pragma unroll
        for (int qq = 0; qq < 8; qq++){
            float4 v = lds128(hbase + (u32)qq * 16u);
            hv[qq*4+0] = v.x; hv[qq*4+1] = v.y; hv[qq*4+2] = v.z; hv[qq*4+3] = v.w;
        }

        const float4 z4  = rz[t & 3];
        const int    tok = rtok[t & 3];

        // i, f, g chains first (their downstream latency hides under o + LDG)
        float i0 = z4.x, f0 = z4.y, g0 = z4.z;
        float i1 = 0.f,  f1 = 0.f,  g1 = 0.f;
        #pragma unroll
        for (int k = 0; k < 16; k++){
            i0 = fmaf(hv[k], wi[k], i0);
            f0 = fmaf(hv[k], wf[k], f0);
            g0 = fmaf(hv[k], wg[k], g0);
        }
        #pragma unroll
        for (int k = 16; k < 32; k++){
            i1 = fmaf(hv[k], wi[k], i1);
            f1 = fmaf(hv[k], wf[k], f1);
            g1 = fmaf(hv[k], wg[k], g1);
        }
        const float gi = sigt(i0 + i1);
        const float gf = sigt(f0 + f1);
        const float gg = tanha(g0 + g1);
        const float cn = fmaf(gf, c, gi * gg);
        const float tc = tanha(cn);

        // prefetch t+3 in the MUFU shadow (ring indices compile-time)
        const int pidx = min(t + 3, SEQ - 1);
        rz[(t + 3) & 3]   = zp[(size_t)pidx * HIDD];
        rtok[(t + 3) & 3] = tptr[pidx];

        // o chains last
        float o0 = z4.w, o1 = 0.f;
        #pragma unroll
        for (int k = 0; k < 16; k++)
            o0 = fmaf(hv[k], wo[k], o0);
        #pragma unroll
        for (int k = 16; k < 32; k++)
            o1 = fmaf(hv[k], wo[k], o1);
        const float go = sigt(o0 + o1);
        const float hn = go * tc;

        const bool m = (tok != 0);
        c = m ? cn : c;
        h = m ? hn : h;

        sts32(haddr, h);                     // next iteration's LDS sees this
        optr[(size_t)t * HIDD] = h;          // coalesced 128B per warp
    }
}

extern "C" void kernel_launch(void* const* d_in, const int* in_sizes, int n_in,
                              void* d_out, int out_size)
{
    (void)in_sizes; (void)n_in; (void)out_size;
    const int*   tokens = (const int*)  d_in[0];
    const float* emb    = (const float*)d_in[1];
    const float* Wk     = (const float*)d_in[2];
    const float* Wr     = (const float*)d_in[3];
    const float* bias   = (const float*)d_in[4];
    float* out = (float*)d_out;

    proj_kernel<<<BATCH, 256>>>(tokens, emb, Wk, bias);
    rec_kernel<<<BATCH / SEQ_PER_BLK, 32 * SEQ_PER_BLK>>>(tokens, Wr, out);
}

// round 11
// speedup vs baseline: 1.3178x; 1.3022x over previous
#include <cuda_runtime.h>

#define BATCH 256
#define SEQ   2048
#define EMBD  16
#define HIDD  32
#define GATE  128
#define SEQ_PER_BLK 4

typedef unsigned long long u64;
typedef unsigned int       u32;

// 256 MB scratch: gate-packed input projection, float4(i,f,g,o) per (token, hid)
__device__ float4 g_zx[(size_t)BATCH * SEQ * HIDD];

__device__ __forceinline__ u64 pack2(float lo, float hi){
    u64 r; asm("mov.b64 %0, {%1,%2};" : "=l"(r) : "f"(lo), "f"(hi)); return r;
}
__device__ __forceinline__ void unpack2(u64 v, float& lo, float& hi){
    asm("mov.b64 {%0,%1}, %2;" : "=f"(lo), "=f"(hi) : "l"(v));
}
__device__ __forceinline__ u64 ffma2(u64 a, u64 b, u64 c){
    u64 d; asm("fma.rn.f32x2 %0, %1, %2, %3;" : "=l"(d) : "l"(a), "l"(b), "l"(c)); return d;
}
__device__ __forceinline__ float tanha(float x){
    float y; asm("tanh.approx.f32 %0, %1;" : "=f"(y) : "f"(x)); return y;
}
// sigmoid(z) = 0.5 + 0.5*tanh(z/2)
__device__ __forceinline__ float sigt(float z){
    return fmaf(0.5f, tanha(0.5f * z), 0.5f);
}
__device__ __forceinline__ u32 smem_u32(const void* p){
    u32 a;
    asm("{ .reg .u64 t; cvta.to.shared.u64 t, %1; cvt.u32.u64 %0, t; }"
        : "=r"(a) : "l"(p));
    return a;
}
__device__ __forceinline__ void sts32(u32 addr, float v){
    asm volatile("st.shared.f32 [%0], %1;" :: "r"(addr), "f"(v) : "memory");
}
__device__ __forceinline__ float4 lds128(u32 addr){
    float4 v;
    asm volatile("ld.shared.v4.f32 {%0,%1,%2,%3}, [%4];"
        : "=f"(v.x), "=f"(v.y), "=f"(v.z), "=f"(v.w) : "r"(addr));
    return v;
}

// ─────────────── Phase 1: zx = emb[tok]@Wk + b  (proven, ~85us) ─────────────
__global__ __launch_bounds__(256) void proj_kernel(
    const int*   __restrict__ tokens,
    const float* __restrict__ emb,
    const float* __restrict__ Wk,
    const float* __restrict__ bias)
{
    const int j    = threadIdx.x & 31;
    const int warp = (blockIdx.x << 3) + (threadIdx.x >> 5);
    const int base = warp << 8;

    u64 wk_if[EMBD], wk_go[EMBD];
    #pragma unroll
    for (int e = 0; e < EMBD; e++){
        wk_if[e] = pack2(Wk[e*GATE + j],      Wk[e*GATE + j + 32]);
        wk_go[e] = pack2(Wk[e*GATE + j + 64], Wk[e*GATE + j + 96]);
    }
    const u64 b_if = pack2(bias[j],      bias[j + 32]);
    const u64 b_go = pack2(bias[j + 64], bias[j + 96]);

    for (int s = 0; s < 256; s += 2){
        const int tflat = base + s + (j >> 4);
        const int tok   = tokens[tflat];
        const float xv  = emb[tok * EMBD + (j & 15)];

        u64 aI = b_if, aG = b_go;
        u64 cI = b_if, cG = b_go;
        #pragma unroll
        for (int e = 0; e < EMBD; e++){
            float xa = __shfl_sync(0xffffffffu, xv, e);
            float xb = __shfl_sync(0xffffffffu, xv, 16 + e);
            u64 xa2 = pack2(xa, xa);
            u64 xb2 = pack2(xb, xb);
            aI = ffma2(xa2, wk_if[e], aI);
            aG = ffma2(xa2, wk_go[e], aG);
            cI = ffma2(xb2, wk_if[e], cI);
            cG = ffma2(xb2, wk_go[e], cG);
        }
        float4 zA, zB;
        unpack2(aI, zA.x, zA.y); unpack2(aG, zA.z, zA.w);
        unpack2(cI, zB.x, zB.y); unpack2(cG, zB.z, zB.w);
        g_zx[(size_t)(base + s)     * HIDD + j] = zA;
        g_zx[(size_t)(base + s + 1) * HIDD + j] = zB;
    }
}

// ─────────────── Phase 2: recurrence, spill-proof hand-unrolled rings ──────
// 4 warps/block, one sequence per warp, each on its own SMSP. NO arrays with
// computed indices anywhere in the loop: ring slots are named scalars (zA..zD,
// tA..tD), hand-unrolled 4x — slot i is consumed and refilled only in body i
// (prefetch distance exactly 4 steps, zero rotation copies). hv[] replaced by
// named float4 h0..h7. Weight arrays use constant indices only.
#define CHAIN4(acc, hh, ww, base)                       \
    acc = fmaf((hh).x, ww[(base)  ], acc);              \
    acc = fmaf((hh).y, ww[(base)+1], acc);              \
    acc = fmaf((hh).z, ww[(base)+2], acc);              \
    acc = fmaf((hh).w, ww[(base)+3], acc);

#define LSTM_BODY(Z, TK, tt)                                            \
{                                                                       \
    const float4 z4  = Z;                                               \
    const int    tok = TK;                                              \
    const int    pidx = min((tt) + 4, SEQ - 1);                         \
    Z  = zp[(size_t)pidx * HIDD];      /* refill slot for step tt+4 */  \
    TK = tptr[pidx];                                                    \
    const float4 h0 = lds128(hbase +   0u);                             \
    const float4 h1 = lds128(hbase +  16u);                             \
    const float4 h2 = lds128(hbase +  32u);                             \
    const float4 h3 = lds128(hbase +  48u);                             \
    const float4 h4 = lds128(hbase +  64u);                             \
    const float4 h5 = lds128(hbase +  80u);                             \
    const float4 h6 = lds128(hbase +  96u);                             \
    const float4 h7 = lds128(hbase + 112u);                             \
    float i0 = z4.x, f0 = z4.y, g0 = z4.z;                              \
    float i1 = 0.f,  f1 = 0.f,  g1 = 0.f;                               \
    CHAIN4(i0, h0, wi, 0)  CHAIN4(f0, h0, wf, 0)  CHAIN4(g0, h0, wg, 0) \
    CHAIN4(i0, h1, wi, 4)  CHAIN4(f0, h1, wf, 4)  CHAIN4(g0, h1, wg, 4) \
    CHAIN4(i0, h2, wi, 8)  CHAIN4(f0, h2, wf, 8)  CHAIN4(g0, h2, wg, 8) \
    CHAIN4(i0, h3, wi,12)  CHAIN4(f0, h3, wf,12)  CHAIN4(g0, h3, wg,12) \
    CHAIN4(i1, h4, wi,16)  CHAIN4(f1, h4, wf,16)  CHAIN4(g1, h4, wg,16) \
    CHAIN4(i1, h5, wi,20)  CHAIN4(f1, h5, wf,20)  CHAIN4(g1, h5, wg,20) \
    CHAIN4(i1, h6, wi,24)  CHAIN4(f1, h6, wf,24)  CHAIN4(g1, h6, wg,24) \
    CHAIN4(i1, h7, wi,28)  CHAIN4(f1, h7, wf,28)  CHAIN4(g1, h7, wg,28) \
    const float gi = sigt(i0 + i1);                                     \
    const float gf = sigt(f0 + f1);                                     \
    const float gg = tanha(g0 + g1);                                    \
    const float cn = fmaf(gf, c, gi * gg);                              \
    const float tc = tanha(cn);                                         \
    float o0 = z4.w, o1 = 0.f;                                          \
    CHAIN4(o0, h0, wo, 0)  CHAIN4(o0, h1, wo, 4)                        \
    CHAIN4(o0, h2, wo, 8)  CHAIN4(o0, h3, wo,12)                        \
    CHAIN4(o1, h4, wo,16)  CHAIN4(o1, h5, wo,20)                        \
    CHAIN4(o1, h6, wo,24)  CHAIN4(o1, h7, wo,28)                        \
    const float go = sigt(o0 + o1);                                     \
    const float hn = go * tc;                                           \
    const bool  m  = (tok != 0);                                        \
    c = m ? cn : c;                                                     \
    h = m ? hn : h;                                                     \
    sts32(haddr, h);                                                    \
    optr[(size_t)(tt) * HIDD] = h;                                      \
}

__global__ __launch_bounds__(128) void rec_kernel(
    const int*   __restrict__ tokens,
    const float* __restrict__ Wr,
    float*       __restrict__ out)
{
    __shared__ float hs[SEQ_PER_BLK][HIDD];

    const int w = threadIdx.x >> 5;
    const int j = threadIdx.x & 31;
    const int b = blockIdx.x * SEQ_PER_BLK + w;

    float wi[HIDD], wf[HIDD], wg[HIDD], wo[HIDD];   // constant indices only
    #pragma unroll
    for (int k = 0; k < HIDD; k++){
        wi[k] = Wr[k*GATE + j];
        wf[k] = Wr[k*GATE + j + 32];
        wg[k] = Wr[k*GATE + j + 64];
        wo[k] = Wr[k*GATE + j + 96];
    }

    const u32 hbase = smem_u32(hs[w]);
    const u32 haddr = hbase + (u32)j * 4u;

    const float4* __restrict__ zp   = g_zx + (size_t)b * SEQ * HIDD + j;
    const int*    __restrict__ tptr = tokens + b * SEQ;
    float* optr = out + (size_t)b * SEQ * HIDD + j;

    // named ring slots: slot i serves steps t ≡ i (mod 4)
    float4 zA = zp[0*HIDD], zB = zp[1*HIDD], zC = zp[2*HIDD], zD = zp[3*HIDD];
    int    tA = tptr[0],    tB = tptr[1],    tC = tptr[2],    tD = tptr[3];

    sts32(haddr, 0.0f);
    float h = 0.0f, c = 0.0f;

    for (int t = 0; t < SEQ; t += 4){
        LSTM_BODY(zA, tA, t + 0)
        LSTM_BODY(zB, tB, t + 1)
        LSTM_BODY(zC, tC, t + 2)
        LSTM_BODY(zD, tD, t + 3)
    }
}

extern "C" void kernel_launch(void* const* d_in, const int* in_sizes, int n_in,
                              void* d_out, int out_size)
{
    (void)in_sizes; (void)n_in; (void)out_size;
    const int*   tokens = (const int*)  d_in[0];
    const float* emb    = (const float*)d_in[1];
    const float* Wk     = (const float*)d_in[2];
    const float* Wr     = (const float*)d_in[3];
    const float* bias   = (const float*)d_in[4];
    float* out = (float*)d_out;

    proj_kernel<<<BATCH, 256>>>(tokens, emb, Wk, bias);
    rec_kernel<<<BATCH / SEQ_PER_BLK, 32 * SEQ_PER_BLK>>>(tokens, Wr, out);
}